// round 14
// baseline (speedup 1.0000x reference)
#include <cuda_runtime.h>
#include <math.h>
#include <cstdint>

#define NSIG   8192
#define DB     512
#define NBAS   2048
#define SCIT   20
#define PMIT   100

// ---------------- device scratch ----------------
__device__ float g_Wf[(size_t)DB * NBAS];          // f32 normalized dict
__device__ float g_Wg0[(size_t)DB * NBAS];         // eta * Wf (for Gamma0 GEMM)
__device__ float g_x[2][NBAS];                     // power-method state (2048-dim)
__device__ float g_t1[DB];
__device__ float g_pmacc[PMIT + 2];
__device__ float g_scal[4];                        // c, 1/c, K/c, K
__device__ float g_nacc[SCIT];
__device__ float g_ysum;
__device__ float g_Z[(size_t)NSIG * NBAS];
__device__ float g_Gamma[(size_t)NSIG * NBAS];
__device__ float g_Gamma2[(size_t)NSIG * NBAS];
__device__ float g_res[(size_t)NSIG * DB];

__device__ __forceinline__ float softf(float x, float lam) {
    float t = fabsf(x) - lam;
    return t > 0.f ? copysignf(t, x) : 0.f;
}
__device__ __forceinline__ unsigned rotl32(unsigned v, int r) {
    return (v << r) | (v >> (32 - r));
}

// jax threefry2x32 with key (0,1)  (jax.random.key(1))
__device__ __forceinline__ void threefry01(unsigned& x0, unsigned& x1) {
    const unsigned ks0 = 0u, ks1 = 1u, ks2 = 0x1BD11BDBu;
    x0 += ks0; x1 += ks1;
#define TFR(r) { x0 += x1; x1 = rotl32(x1, (r)); x1 ^= x0; }
    TFR(13) TFR(15) TFR(26) TFR(6)   x0 += ks1; x1 += ks2 + 1u;
    TFR(17) TFR(29) TFR(16) TFR(24)  x0 += ks2; x1 += ks0 + 2u;
    TFR(13) TFR(15) TFR(26) TFR(6)   x0 += ks0; x1 += ks1 + 3u;
    TFR(17) TFR(29) TFR(16) TFR(24)  x0 += ks1; x1 += ks2 + 4u;
    TFR(13) TFR(15) TFR(26) TFR(6)   x0 += ks2; x1 += ks0 + 5u;
#undef TFR
}

// bits -> uniform(nextafter(-1,0),1) -> sqrt(2)*erfinv  (XLA f32 poly)
__device__ float bits_to_normal(unsigned b) {
    float f = __uint_as_float((b >> 9) | 0x3F800000u) - 1.0f;
    const float lo = -0.99999994f;
    float u = fmaxf(lo, fmaf(f, 2.0f, lo));
    float w = -log1pf(-u * u), p;
    if (w < 5.0f) {
        w -= 2.5f;
        p = 2.81022636e-08f;
        p = fmaf(p, w, 3.43273939e-07f);  p = fmaf(p, w, -3.5233877e-06f);
        p = fmaf(p, w, -4.39150654e-06f); p = fmaf(p, w, 0.00021858087f);
        p = fmaf(p, w, -0.00125372503f);  p = fmaf(p, w, -0.00417768164f);
        p = fmaf(p, w, 0.246640727f);     p = fmaf(p, w, 1.50140941f);
    } else {
        w = sqrtf(w) - 3.0f;
        p = -0.000200214257f;
        p = fmaf(p, w, 0.000100950558f);  p = fmaf(p, w, 0.00134934322f);
        p = fmaf(p, w, -0.00367342844f);  p = fmaf(p, w, 0.00573950773f);
        p = fmaf(p, w, -0.0076224613f);   p = fmaf(p, w, 0.00943887047f);
        p = fmaf(p, w, 1.00167406f);      p = fmaf(p, w, 2.83297682f);
    }
    return 1.41421356237f * (p * u);
}

// ---------------- small kernels ----------------
__global__ void k_init() {
    int t = threadIdx.x;
    if (t < PMIT + 2) g_pmacc[t] = 0.f;
    if (t < SCIT)     g_nacc[t]  = 0.f;
    if (t == 0)       g_ysum     = 0.f;
}

__global__ void k_ysum(const float* __restrict__ Y) {
    __shared__ float red[256];
    float s = 0.f;
    for (size_t i = (size_t)blockIdx.x * blockDim.x + threadIdx.x;
         i < (size_t)NSIG * DB; i += (size_t)gridDim.x * blockDim.x) {
        float v = Y[i]; s += v * v;
    }
    red[threadIdx.x] = s; __syncthreads();
    for (int o = 128; o > 0; o >>= 1) {
        if (threadIdx.x < o) red[threadIdx.x] += red[threadIdx.x + o];
        __syncthreads();
    }
    if (threadIdx.x == 0) atomicAdd(&g_ysum, red[0]);
}

__global__ void k_normw(const float* __restrict__ W) {
    int j = blockIdx.x * blockDim.x + threadIdx.x;
    if (j >= NBAS) return;
    float s = 0.f;
    for (int i = 0; i < DB; i++) { float v = W[(size_t)i * NBAS + j]; s += v * v; }
    float n = sqrtf(s);
    for (int i = 0; i < DB; i++)
        g_Wf[(size_t)i * NBAS + j] = W[(size_t)i * NBAS + j] / n;
}

__global__ void k_wg0() {   // Wg0 = eta * Wf  (matches Y @ (eta*W) dataflow)
    size_t i = (size_t)blockIdx.x * blockDim.x + threadIdx.x;
    if (i < (size_t)DB * NBAS) g_Wg0[i] = __fmul_rn(g_scal[1], g_Wf[i]);
}

// PARTITIONABLE threefry (jax_threefry_partitionable=True, modern jax default):
// per element i: counter = (hi=0, lo=i); 32-bit bits = out0 ^ out1
__global__ void k_x0() {
    int i = blockIdx.x * blockDim.x + threadIdx.x;
    if (i >= NBAS) return;
    unsigned x0 = 0u, x1 = (unsigned)i;
    threefry01(x0, x1);
    g_x[0][i] = bits_to_normal(x0 ^ x1);
}

// t1[d] = sum_m (x[m]/nm) * Wf[d,m]   (pure f32)
__global__ void k_pma(int k) {
    __shared__ float xs[NBAS];
    float nm = (k == 1) ? 1.0f : sqrtf(g_pmacc[k - 1]);
    const float* x = g_x[(k - 1) & 1];
    for (int m = threadIdx.x; m < NBAS; m += blockDim.x) xs[m] = x[m] / nm;
    __syncthreads();
    int warp = threadIdx.x >> 5, lane = threadIdx.x & 31;
    int d = blockIdx.x * 8 + warp;
    const float* row = &g_Wf[(size_t)d * NBAS];
    float s = 0.f;
    for (int m = lane; m < NBAS; m += 32) s += xs[m] * row[m];
#pragma unroll
    for (int o = 16; o; o >>= 1) s += __shfl_down_sync(0xffffffffu, s, o);
    if (lane == 0) g_t1[d] = s;
}

// x'[m] = sum_d t1[d] * Wf[d,m];  pmacc[k] = ||x'||^2
__global__ void k_pmb(int k) {
    __shared__ float ts[DB];
    __shared__ float red[256];
    for (int d = threadIdx.x; d < DB; d += blockDim.x) ts[d] = g_t1[d];
    __syncthreads();
    int t = blockIdx.x * blockDim.x + threadIdx.x;   // 8192 threads total
    int m = t >> 2, q = t & 3;
    const float* col = &g_Wf[(size_t)(q * 128) * NBAS + m];
    float v = 0.f;
#pragma unroll 8
    for (int d = 0; d < 128; d++) v += ts[q * 128 + d] * col[(size_t)d * NBAS];
    v += __shfl_xor_sync(0xffffffffu, v, 1);
    v += __shfl_xor_sync(0xffffffffu, v, 2);
    float ssv = 0.f;
    if (q == 0) { g_x[k & 1][m] = v; ssv = v * v; }
    red[threadIdx.x] = ssv; __syncthreads();
    for (int o = 128; o > 0; o >>= 1) {
        if (threadIdx.x < o) red[threadIdx.x] += red[threadIdx.x + o];
        __syncthreads();
    }
    if (threadIdx.x == 0) atomicAdd(&g_pmacc[k], red[0]);
}

__global__ void k_scal(const float* __restrict__ Kp) {
    float c = sqrtf(g_pmacc[PMIT]);
    float K = *Kp;
    g_scal[0] = c; g_scal[1] = 1.0f / c; g_scal[2] = K / c; g_scal[3] = K;
}

__global__ void k_norms(float* __restrict__ out) {
    int i = threadIdx.x;
    if (i < SCIT) out[i] = sqrtf(g_nacc[i]) / sqrtf(g_ysum);
}

// ---------------- tiled f32 SGEMM + fused epilogues ----------------
// C[m,n] = sum_k A[m,k]*B[k,n];  BT: B[k,n] = Bsrc[n*Kd + k]
enum { M_PLAIN = 0, M_RES = 1, M_G0 = 2, M_UPD = 3 };

template <int MODE, bool BT>
__global__ __launch_bounds__(256)
void sgemm(const float* __restrict__ A, const float* __restrict__ Bsrc,
           float* __restrict__ C, int Kd, int Nn,
           const float* __restrict__ Yp, float* __restrict__ Zp,
           const float* __restrict__ Gold, float* __restrict__ nacc,
           float mcoef)
{
    __shared__ __align__(16) float As[16][128];
    __shared__ __align__(16) float Bs[16][128];

    const int tid = threadIdx.x;
    const int tx = tid & 15, ty = tid >> 4;
    const int m0 = blockIdx.y * 128, n0 = blockIdx.x * 128;

    const int a_row = tid >> 2;
    const int a_col = (tid & 3) << 2;
    const float* Ag = A + (size_t)(m0 + a_row) * Kd + a_col;

    int b_row, b_col;
    const float* Bg;
    if (BT) {
        b_col = tid >> 1; b_row = (tid & 1) << 3;
        Bg = Bsrc + (size_t)(n0 + b_col) * Kd + b_row;
    } else {
        b_row = tid >> 5; b_col = (tid & 31) << 2;
        Bg = Bsrc + (size_t)b_row * Nn + n0 + b_col;
    }

    float acc[8][8];
#pragma unroll
    for (int i = 0; i < 8; i++)
#pragma unroll
        for (int j = 0; j < 8; j++) acc[i][j] = 0.f;

    float4 a0 = *(const float4*)(Ag);
    float4 a1 = *(const float4*)(Ag + (size_t)64 * Kd);
    float4 b0, b1;
    if (BT) { b0 = *(const float4*)(Bg); b1 = *(const float4*)(Bg + 4); }
    else    { b0 = *(const float4*)(Bg); b1 = *(const float4*)(Bg + (size_t)8 * Nn); }

    const int ktiles = Kd >> 4;
    for (int kt = 0; kt < ktiles; kt++) {
        __syncthreads();
        As[a_col + 0][a_row] = a0.x; As[a_col + 1][a_row] = a0.y;
        As[a_col + 2][a_row] = a0.z; As[a_col + 3][a_row] = a0.w;
        As[a_col + 0][a_row + 64] = a1.x; As[a_col + 1][a_row + 64] = a1.y;
        As[a_col + 2][a_row + 64] = a1.z; As[a_col + 3][a_row + 64] = a1.w;
        if (BT) {
            Bs[b_row + 0][b_col] = b0.x; Bs[b_row + 1][b_col] = b0.y;
            Bs[b_row + 2][b_col] = b0.z; Bs[b_row + 3][b_col] = b0.w;
            Bs[b_row + 4][b_col] = b1.x; Bs[b_row + 5][b_col] = b1.y;
            Bs[b_row + 6][b_col] = b1.z; Bs[b_row + 7][b_col] = b1.w;
        } else {
            *(float4*)&Bs[b_row][b_col]     = b0;
            *(float4*)&Bs[b_row + 8][b_col] = b1;
        }
        __syncthreads();

        if (kt + 1 < ktiles) {
            const float* Ag2 = Ag + ((size_t)(kt + 1) << 4);
            a0 = *(const float4*)(Ag2);
            a1 = *(const float4*)(Ag2 + (size_t)64 * Kd);
            if (BT) {
                const float* Bg2 = Bg + ((size_t)(kt + 1) << 4);
                b0 = *(const float4*)(Bg2); b1 = *(const float4*)(Bg2 + 4);
            } else {
                const float* Bg2 = Bg + ((size_t)(kt + 1) << 4) * Nn;
                b0 = *(const float4*)(Bg2); b1 = *(const float4*)(Bg2 + (size_t)8 * Nn);
            }
        }

#pragma unroll
        for (int k = 0; k < 16; k++) {
            float af[8], bf[8];
            *(float4*)&af[0] = *(float4*)&As[k][ty * 8];
            *(float4*)&af[4] = *(float4*)&As[k][ty * 8 + 4];
            *(float4*)&bf[0] = *(float4*)&Bs[k][tx * 8];
            *(float4*)&bf[4] = *(float4*)&Bs[k][tx * 8 + 4];
#pragma unroll
            for (int i = 0; i < 8; i++)
#pragma unroll
                for (int j = 0; j < 8; j++)
                    acc[i][j] = fmaf(af[i], bf[j], acc[i][j]);
        }
    }

    // ---- epilogue ----
    float etav = 0.f, lamv = 0.f, ss = 0.f;
    if (MODE == M_G0)  { lamv = g_scal[3]; }                   // B already eta-scaled
    if (MODE == M_UPD) { etav = g_scal[1]; lamv = g_scal[2]; }

#pragma unroll
    for (int i = 0; i < 8; i++) {
        size_t base = (size_t)(m0 + ty * 8 + i) * (size_t)Nn + n0 + tx * 8;
#pragma unroll
        for (int h = 0; h < 2; h++) {
            size_t idx = base + h * 4;
            float rr[4] = { acc[i][h*4], acc[i][h*4+1], acc[i][h*4+2], acc[i][h*4+3] };
            if (MODE == M_PLAIN) {
                float4 r = make_float4(rr[0], rr[1], rr[2], rr[3]);
                *(float4*)&C[idx] = r;
            } else if (MODE == M_RES) {
                float4 y = *(const float4*)&Yp[idx];
                float4 r;
                r.x = __fsub_rn(rr[0], y.x); r.y = __fsub_rn(rr[1], y.y);
                r.z = __fsub_rn(rr[2], y.z); r.w = __fsub_rn(rr[3], y.w);
                *(float4*)&C[idx] = r;
                ss += r.x*r.x + r.y*r.y + r.z*r.z + r.w*r.w;
            } else if (MODE == M_G0) {
                float4 g = make_float4(softf(rr[0], lamv), softf(rr[1], lamv),
                                       softf(rr[2], lamv), softf(rr[3], lamv));
                *(float4*)&C[idx]  = g;
                *(float4*)&Zp[idx] = g;
            } else { // M_UPD — unfused rn ops, C/Gold distinct ping-pong buffers
                float4 z  = *(const float4*)&Zp[idx];
                float4 go = *(const float4*)&Gold[idx];
                float zf[4] = { z.x, z.y, z.z, z.w };
                float gf[4] = { go.x, go.y, go.z, go.w };
                float4 g, zn;
                float* gp = &g.x; float* zp = &zn.x;
#pragma unroll
                for (int q = 0; q < 4; q++) {
                    float t1 = __fmul_rn(etav, rr[q]);
                    float za = __fsub_rn(zf[q], t1);
                    float gv = softf(za, lamv);
                    float dd = __fsub_rn(gv, gf[q]);
                    float mm = __fmul_rn(mcoef, dd);
                    gp[q] = gv;
                    zp[q] = __fadd_rn(gv, mm);
                }
                *(float4*)&C[idx]  = g;
                *(float4*)&Zp[idx] = zn;
            }
        }
    }

    if (MODE == M_RES) {
        __syncthreads();
        float* red = &As[0][0];
        red[tid] = ss; __syncthreads();
        for (int o = 128; o > 0; o >>= 1) {
            if (tid < o) red[tid] += red[tid + o];
            __syncthreads();
        }
        if (tid == 0) atomicAdd(nacc, red[0]);
    }
}

// ---------------- launch ----------------
static float* symaddr(const void* s) {
    void* p = nullptr;
    cudaGetSymbolAddress(&p, s);
    return (float*)p;
}

extern "C" void kernel_launch(void* const* d_in, const int* in_sizes, int n_in,
                              void* d_out, int out_size) {
    const float *Y = nullptr, *W = nullptr, *Kp = nullptr;
    for (int i = 0; i < n_in; i++) {
        if (in_sizes[i] == NSIG * DB)      Y  = (const float*)d_in[i];
        else if (in_sizes[i] == DB * NBAS) W  = (const float*)d_in[i];
        else                               Kp = (const float*)d_in[i];
    }
    float* out  = (float*)d_out;
    float* outX = out;
    float* outG = out + (size_t)NSIG * DB;
    float* outN = outG + (size_t)NSIG * NBAS;

    float* pWf   = symaddr(g_Wf);
    float* pWg0  = symaddr(g_Wg0);
    float* pZ    = symaddr(g_Z);
    float* pRes  = symaddr(g_res);
    float* pNacc = symaddr(g_nacc);
    float* Gbuf[2] = { symaddr(g_Gamma), symaddr(g_Gamma2) };

    k_init<<<1, 256>>>();
    k_normw<<<16, 128>>>(W);
    k_ysum<<<256, 256>>>(Y);
    k_x0<<<8, 256>>>();                         // partitionable threefry seed
    for (int k = 1; k <= PMIT; k++) {           // pure-f32 power method
        k_pma<<<64, 256>>>(k);
        k_pmb<<<32, 256>>>(k);
    }
    k_scal<<<1, 1>>>(Kp);
    k_wg0<<<(DB * NBAS + 255) / 256, 256>>>();  // Wg0 = eta*Wf

    // Gamma0 = soft(Y @ (eta*Wf), K) -> Gbuf[0], Z
    sgemm<M_G0, false><<<dim3(16, 64), 256>>>(Y, pWg0, Gbuf[0], DB, NBAS,
                                              nullptr, pZ, nullptr, nullptr, 0.f);

    float t = 1.0f;
    for (int it = 0; it < SCIT; it++) {
        // residual = Z@Wf^T - Y ; accumulate ||residual||^2
        sgemm<M_RES, true><<<dim3(4, 64), 256>>>(pZ, pWf, pRes, NBAS, DB,
                                                 Y, nullptr, nullptr, pNacc + it, 0.f);
        float t_new = (1.0f + sqrtf(1.0f + 4.0f * t * t)) * 0.5f;
        float mcoef = (t - 1.0f) / t_new;
        t = t_new;
        float* gold = Gbuf[it & 1];
        float* gout = (it == SCIT - 1) ? outG : Gbuf[(it + 1) & 1];
        // Gamma_new = soft(Z - eta*(residual@Wf), K/c); Z = Gn + mcoef*(Gn - Gold)
        sgemm<M_UPD, false><<<dim3(16, 64), 256>>>(pRes, pWf, gout, DB, NBAS,
                                                   nullptr, pZ, gold, nullptr, mcoef);
    }

    // X = Gamma @ Wf^T
    sgemm<M_PLAIN, true><<<dim3(4, 64), 256>>>(outG, pWf, outX, NBAS, DB,
                                               nullptr, nullptr, nullptr, nullptr, 0.f);
    k_norms<<<1, 32>>>(outN);
    (void)out_size;
}

// round 15
// speedup vs baseline: 1.0477x; 1.0477x over previous
#include <cuda_runtime.h>
#include <math.h>
#include <cstdint>

#define NSIG   8192
#define DB     512
#define NBAS   2048
#define SCIT   20
#define PMIT   100

// ---------------- device scratch ----------------
__device__ float g_Wf[(size_t)DB * NBAS];          // f32 normalized dict
__device__ float g_Wg0[(size_t)DB * NBAS];         // eta * Wf (for Gamma0 GEMM)
__device__ float g_x[2][NBAS];                     // power-method state (2048-dim)
__device__ float g_t1[DB];
__device__ float g_pmacc[PMIT + 2];
__device__ float g_scal[4];                        // c, 1/c, K/c, K
__device__ float g_nacc[SCIT];
__device__ float g_ysum;
__device__ float g_Z[(size_t)NSIG * NBAS];
__device__ float g_Gamma[(size_t)NSIG * NBAS];
__device__ float g_Gamma2[(size_t)NSIG * NBAS];
__device__ float g_res[(size_t)NSIG * DB];

__device__ __forceinline__ float softf(float x, float lam) {
    float t = fabsf(x) - lam;
    return t > 0.f ? copysignf(t, x) : 0.f;
}
__device__ __forceinline__ unsigned rotl32(unsigned v, int r) {
    return (v << r) | (v >> (32 - r));
}

// jax threefry2x32 with key (0,1)  (jax.random.key(1))
__device__ __forceinline__ void threefry01(unsigned& x0, unsigned& x1) {
    const unsigned ks0 = 0u, ks1 = 1u, ks2 = 0x1BD11BDBu;
    x0 += ks0; x1 += ks1;
#define TFR(r) { x0 += x1; x1 = rotl32(x1, (r)); x1 ^= x0; }
    TFR(13) TFR(15) TFR(26) TFR(6)   x0 += ks1; x1 += ks2 + 1u;
    TFR(17) TFR(29) TFR(16) TFR(24)  x0 += ks2; x1 += ks0 + 2u;
    TFR(13) TFR(15) TFR(26) TFR(6)   x0 += ks0; x1 += ks1 + 3u;
    TFR(17) TFR(29) TFR(16) TFR(24)  x0 += ks1; x1 += ks2 + 4u;
    TFR(13) TFR(15) TFR(26) TFR(6)   x0 += ks2; x1 += ks0 + 5u;
#undef TFR
}

// bits -> uniform(nextafter(-1,0),1) -> sqrt(2)*erfinv  (XLA f32 poly)
__device__ float bits_to_normal(unsigned b) {
    float f = __uint_as_float((b >> 9) | 0x3F800000u) - 1.0f;
    const float lo = -0.99999994f;
    float u = fmaxf(lo, fmaf(f, 2.0f, lo));
    float w = -log1pf(-u * u), p;
    if (w < 5.0f) {
        w -= 2.5f;
        p = 2.81022636e-08f;
        p = fmaf(p, w, 3.43273939e-07f);  p = fmaf(p, w, -3.5233877e-06f);
        p = fmaf(p, w, -4.39150654e-06f); p = fmaf(p, w, 0.00021858087f);
        p = fmaf(p, w, -0.00125372503f);  p = fmaf(p, w, -0.00417768164f);
        p = fmaf(p, w, 0.246640727f);     p = fmaf(p, w, 1.50140941f);
    } else {
        w = sqrtf(w) - 3.0f;
        p = -0.000200214257f;
        p = fmaf(p, w, 0.000100950558f);  p = fmaf(p, w, 0.00134934322f);
        p = fmaf(p, w, -0.00367342844f);  p = fmaf(p, w, 0.00573950773f);
        p = fmaf(p, w, -0.0076224613f);   p = fmaf(p, w, 0.00943887047f);
        p = fmaf(p, w, 1.00167406f);      p = fmaf(p, w, 2.83297682f);
    }
    return 1.41421356237f * (p * u);
}

// ---------------- small kernels ----------------
__global__ void k_init() {
    int t = threadIdx.x;
    if (t < PMIT + 2) g_pmacc[t] = 0.f;
    if (t < SCIT)     g_nacc[t]  = 0.f;
    if (t == 0)       g_ysum     = 0.f;
}

__global__ void k_ysum(const float* __restrict__ Y) {
    __shared__ float red[256];
    float s = 0.f;
    for (size_t i = (size_t)blockIdx.x * blockDim.x + threadIdx.x;
         i < (size_t)NSIG * DB; i += (size_t)gridDim.x * blockDim.x) {
        float v = Y[i]; s += v * v;
    }
    red[threadIdx.x] = s; __syncthreads();
    for (int o = 128; o > 0; o >>= 1) {
        if (threadIdx.x < o) red[threadIdx.x] += red[threadIdx.x + o];
        __syncthreads();
    }
    if (threadIdx.x == 0) atomicAdd(&g_ysum, red[0]);
}

__global__ void k_normw(const float* __restrict__ W) {
    int j = blockIdx.x * blockDim.x + threadIdx.x;
    if (j >= NBAS) return;
    float s = 0.f;
    for (int i = 0; i < DB; i++) { float v = W[(size_t)i * NBAS + j]; s += v * v; }
    float n = sqrtf(s);
    for (int i = 0; i < DB; i++)
        g_Wf[(size_t)i * NBAS + j] = W[(size_t)i * NBAS + j] / n;
}

__global__ void k_wg0() {   // Wg0 = eta * Wf  (matches Y @ (eta*W) dataflow)
    size_t i = (size_t)blockIdx.x * blockDim.x + threadIdx.x;
    if (i < (size_t)DB * NBAS) g_Wg0[i] = __fmul_rn(g_scal[1], g_Wf[i]);
}

// PARTITIONABLE threefry (jax_threefry_partitionable=True, modern jax default):
// per element i: counter = (hi=0, lo=i); 32-bit bits = out0 ^ out1
__global__ void k_x0() {
    int i = blockIdx.x * blockDim.x + threadIdx.x;
    if (i >= NBAS) return;
    unsigned x0 = 0u, x1 = (unsigned)i;
    threefry01(x0, x1);
    g_x[0][i] = bits_to_normal(x0 ^ x1);
}

// t1[d] = sum_m (x[m]/nm) * Wf[d,m]   (pure f32)
__global__ void k_pma(int k) {
    __shared__ float xs[NBAS];
    float nm = (k == 1) ? 1.0f : sqrtf(g_pmacc[k - 1]);
    const float* x = g_x[(k - 1) & 1];
    for (int m = threadIdx.x; m < NBAS; m += blockDim.x) xs[m] = x[m] / nm;
    __syncthreads();
    int warp = threadIdx.x >> 5, lane = threadIdx.x & 31;
    int d = blockIdx.x * 8 + warp;
    const float* row = &g_Wf[(size_t)d * NBAS];
    float s = 0.f;
    for (int m = lane; m < NBAS; m += 32) s += xs[m] * row[m];
#pragma unroll
    for (int o = 16; o; o >>= 1) s += __shfl_down_sync(0xffffffffu, s, o);
    if (lane == 0) g_t1[d] = s;
}

// x'[m] = sum_d t1[d] * Wf[d,m];  pmacc[k] = ||x'||^2
__global__ void k_pmb(int k) {
    __shared__ float ts[DB];
    __shared__ float red[256];
    for (int d = threadIdx.x; d < DB; d += blockDim.x) ts[d] = g_t1[d];
    __syncthreads();
    int t = blockIdx.x * blockDim.x + threadIdx.x;   // 8192 threads total
    int m = t >> 2, q = t & 3;
    const float* col = &g_Wf[(size_t)(q * 128) * NBAS + m];
    float v = 0.f;
#pragma unroll 8
    for (int d = 0; d < 128; d++) v += ts[q * 128 + d] * col[(size_t)d * NBAS];
    v += __shfl_xor_sync(0xffffffffu, v, 1);
    v += __shfl_xor_sync(0xffffffffu, v, 2);
    float ssv = 0.f;
    if (q == 0) { g_x[k & 1][m] = v; ssv = v * v; }
    red[threadIdx.x] = ssv; __syncthreads();
    for (int o = 128; o > 0; o >>= 1) {
        if (threadIdx.x < o) red[threadIdx.x] += red[threadIdx.x + o];
        __syncthreads();
    }
    if (threadIdx.x == 0) atomicAdd(&g_pmacc[k], red[0]);
}

__global__ void k_scal(const float* __restrict__ Kp) {
    float c = sqrtf(g_pmacc[PMIT]);
    float K = *Kp;
    g_scal[0] = c; g_scal[1] = 1.0f / c; g_scal[2] = K / c; g_scal[3] = K;
}

__global__ void k_norms(float* __restrict__ out) {
    int i = threadIdx.x;
    if (i < SCIT) out[i] = sqrtf(g_nacc[i]) / sqrtf(g_ysum);
}

// ---------------- tiled f32 SGEMM + fused epilogues ----------------
// C[m,n] = sum_k A[m,k]*B[k,n];  BT: B[k,n] = Bsrc[n*Kd + k]
enum { M_PLAIN = 0, M_RES = 1, M_G0 = 2, M_UPD = 3 };

template <int MODE, bool BT>
__global__ __launch_bounds__(256)
void sgemm(const float* __restrict__ A, const float* __restrict__ Bsrc,
           float* __restrict__ C, int Kd, int Nn,
           const float* __restrict__ Yp, float* __restrict__ Zp,
           const float* __restrict__ Gold, float* __restrict__ nacc,
           float mcoef)
{
    __shared__ __align__(16) float As[16][128];
    __shared__ __align__(16) float Bs[16][128];

    const int tid = threadIdx.x;
    const int tx = tid & 15, ty = tid >> 4;
    const int m0 = blockIdx.y * 128, n0 = blockIdx.x * 128;

    const int a_row = tid >> 2;
    const int a_col = (tid & 3) << 2;
    const float* Ag = A + (size_t)(m0 + a_row) * Kd + a_col;

    int b_row, b_col;
    const float* Bg;
    if (BT) {
        b_col = tid >> 1; b_row = (tid & 1) << 3;
        Bg = Bsrc + (size_t)(n0 + b_col) * Kd + b_row;
    } else {
        b_row = tid >> 5; b_col = (tid & 31) << 2;
        Bg = Bsrc + (size_t)b_row * Nn + n0 + b_col;
    }

    float acc[8][8];
#pragma unroll
    for (int i = 0; i < 8; i++)
#pragma unroll
        for (int j = 0; j < 8; j++) acc[i][j] = 0.f;

    float4 a0 = *(const float4*)(Ag);
    float4 a1 = *(const float4*)(Ag + (size_t)64 * Kd);
    float4 b0, b1;
    if (BT) { b0 = *(const float4*)(Bg); b1 = *(const float4*)(Bg + 4); }
    else    { b0 = *(const float4*)(Bg); b1 = *(const float4*)(Bg + (size_t)8 * Nn); }

    const int ktiles = Kd >> 4;
    for (int kt = 0; kt < ktiles; kt++) {
        __syncthreads();
        As[a_col + 0][a_row] = a0.x; As[a_col + 1][a_row] = a0.y;
        As[a_col + 2][a_row] = a0.z; As[a_col + 3][a_row] = a0.w;
        As[a_col + 0][a_row + 64] = a1.x; As[a_col + 1][a_row + 64] = a1.y;
        As[a_col + 2][a_row + 64] = a1.z; As[a_col + 3][a_row + 64] = a1.w;
        if (BT) {
            Bs[b_row + 0][b_col] = b0.x; Bs[b_row + 1][b_col] = b0.y;
            Bs[b_row + 2][b_col] = b0.z; Bs[b_row + 3][b_col] = b0.w;
            Bs[b_row + 4][b_col] = b1.x; Bs[b_row + 5][b_col] = b1.y;
            Bs[b_row + 6][b_col] = b1.z; Bs[b_row + 7][b_col] = b1.w;
        } else {
            *(float4*)&Bs[b_row][b_col]     = b0;
            *(float4*)&Bs[b_row + 8][b_col] = b1;
        }
        __syncthreads();

        if (kt + 1 < ktiles) {
            const float* Ag2 = Ag + ((size_t)(kt + 1) << 4);
            a0 = *(const float4*)(Ag2);
            a1 = *(const float4*)(Ag2 + (size_t)64 * Kd);
            if (BT) {
                const float* Bg2 = Bg + ((size_t)(kt + 1) << 4);
                b0 = *(const float4*)(Bg2); b1 = *(const float4*)(Bg2 + 4);
            } else {
                const float* Bg2 = Bg + ((size_t)(kt + 1) << 4) * Nn;
                b0 = *(const float4*)(Bg2); b1 = *(const float4*)(Bg2 + (size_t)8 * Nn);
            }
        }

#pragma unroll
        for (int k = 0; k < 16; k++) {
            float af[8], bf[8];
            *(float4*)&af[0] = *(float4*)&As[k][ty * 8];
            *(float4*)&af[4] = *(float4*)&As[k][ty * 8 + 4];
            *(float4*)&bf[0] = *(float4*)&Bs[k][tx * 8];
            *(float4*)&bf[4] = *(float4*)&Bs[k][tx * 8 + 4];
#pragma unroll
            for (int i = 0; i < 8; i++)
#pragma unroll
                for (int j = 0; j < 8; j++)
                    acc[i][j] = fmaf(af[i], bf[j], acc[i][j]);
        }
    }

    // ---- epilogue ----
    float etav = 0.f, lamv = 0.f, ss = 0.f;
    if (MODE == M_G0)  { lamv = g_scal[3]; }                   // B already eta-scaled
    if (MODE == M_UPD) { etav = g_scal[1]; lamv = g_scal[2]; }

#pragma unroll
    for (int i = 0; i < 8; i++) {
        size_t base = (size_t)(m0 + ty * 8 + i) * (size_t)Nn + n0 + tx * 8;
#pragma unroll
        for (int h = 0; h < 2; h++) {
            size_t idx = base + h * 4;
            float rr[4] = { acc[i][h*4], acc[i][h*4+1], acc[i][h*4+2], acc[i][h*4+3] };
            if (MODE == M_PLAIN) {
                float4 r = make_float4(rr[0], rr[1], rr[2], rr[3]);
                *(float4*)&C[idx] = r;
            } else if (MODE == M_RES) {
                float4 y = *(const float4*)&Yp[idx];
                float4 r;
                r.x = __fsub_rn(rr[0], y.x); r.y = __fsub_rn(rr[1], y.y);
                r.z = __fsub_rn(rr[2], y.z); r.w = __fsub_rn(rr[3], y.w);
                *(float4*)&C[idx] = r;
                ss += r.x*r.x + r.y*r.y + r.z*r.z + r.w*r.w;
            } else if (MODE == M_G0) {
                float4 g = make_float4(softf(rr[0], lamv), softf(rr[1], lamv),
                                       softf(rr[2], lamv), softf(rr[3], lamv));
                *(float4*)&C[idx]  = g;
                *(float4*)&Zp[idx] = g;
            } else { // M_UPD — unfused rn ops, C/Gold distinct ping-pong buffers
                float4 z  = *(const float4*)&Zp[idx];
                float4 go = *(const float4*)&Gold[idx];
                float zf[4] = { z.x, z.y, z.z, z.w };
                float gf[4] = { go.x, go.y, go.z, go.w };
                float4 g, zn;
                float* gp = &g.x; float* zp = &zn.x;
#pragma unroll
                for (int q = 0; q < 4; q++) {
                    float t1 = __fmul_rn(etav, rr[q]);
                    float za = __fsub_rn(zf[q], t1);
                    float gv = softf(za, lamv);
                    float dd = __fsub_rn(gv, gf[q]);
                    float mm = __fmul_rn(mcoef, dd);
                    gp[q] = gv;
                    zp[q] = __fadd_rn(gv, mm);
                }
                *(float4*)&C[idx]  = g;
                *(float4*)&Zp[idx] = zn;
            }
        }
    }

    if (MODE == M_RES) {
        __syncthreads();
        float* red = &As[0][0];
        red[tid] = ss; __syncthreads();
        for (int o = 128; o > 0; o >>= 1) {
            if (tid < o) red[tid] += red[tid + o];
            __syncthreads();
        }
        if (tid == 0) atomicAdd(nacc, red[0]);
    }
}

// ---------------- launch ----------------
static float* symaddr(const void* s) {
    void* p = nullptr;
    cudaGetSymbolAddress(&p, s);
    return (float*)p;
}

extern "C" void kernel_launch(void* const* d_in, const int* in_sizes, int n_in,
                              void* d_out, int out_size) {
    const float *Y = nullptr, *W = nullptr, *Kp = nullptr;
    for (int i = 0; i < n_in; i++) {
        if (in_sizes[i] == NSIG * DB)      Y  = (const float*)d_in[i];
        else if (in_sizes[i] == DB * NBAS) W  = (const float*)d_in[i];
        else                               Kp = (const float*)d_in[i];
    }
    float* out  = (float*)d_out;
    float* outX = out;
    float* outG = out + (size_t)NSIG * DB;
    float* outN = outG + (size_t)NSIG * NBAS;

    float* pWf   = symaddr(g_Wf);
    float* pWg0  = symaddr(g_Wg0);
    float* pZ    = symaddr(g_Z);
    float* pRes  = symaddr(g_res);
    float* pNacc = symaddr(g_nacc);
    float* Gbuf[2] = { symaddr(g_Gamma), symaddr(g_Gamma2) };

    k_init<<<1, 256>>>();
    k_normw<<<16, 128>>>(W);
    k_ysum<<<256, 256>>>(Y);
    k_x0<<<8, 256>>>();                         // partitionable threefry seed
    for (int k = 1; k <= PMIT; k++) {           // pure-f32 power method
        k_pma<<<64, 256>>>(k);
        k_pmb<<<32, 256>>>(k);
    }
    k_scal<<<1, 1>>>(Kp);
    k_wg0<<<(DB * NBAS + 255) / 256, 256>>>();  // Wg0 = eta*Wf

    // Gamma0 = soft(Y @ (eta*Wf), K) -> Gbuf[0], Z
    sgemm<M_G0, false><<<dim3(16, 64), 256>>>(Y, pWg0, Gbuf[0], DB, NBAS,
                                              nullptr, pZ, nullptr, nullptr, 0.f);

    float t = 1.0f;
    for (int it = 0; it < SCIT; it++) {
        // residual = Z@Wf^T - Y ; accumulate ||residual||^2
        sgemm<M_RES, true><<<dim3(4, 64), 256>>>(pZ, pWf, pRes, NBAS, DB,
                                                 Y, nullptr, nullptr, pNacc + it, 0.f);
        float t_new = (1.0f + sqrtf(1.0f + 4.0f * t * t)) * 0.5f;
        float mcoef = (t - 1.0f) / t_new;
        t = t_new;
        float* gold = Gbuf[it & 1];
        float* gout = (it == SCIT - 1) ? outG : Gbuf[(it + 1) & 1];
        // Gamma_new = soft(Z - eta*(residual@Wf), K/c); Z = Gn + mcoef*(Gn - Gold)
        sgemm<M_UPD, false><<<dim3(16, 64), 256>>>(pRes, pWf, gout, DB, NBAS,
                                                   nullptr, pZ, gold, nullptr, mcoef);
    }

    // X = Gamma @ Wf^T
    sgemm<M_PLAIN, true><<<dim3(4, 64), 256>>>(outG, pWf, outX, NBAS, DB,
                                               nullptr, nullptr, nullptr, nullptr, 0.f);
    k_norms<<<1, 32>>>(outN);
    (void)out_size;
}

// round 17
// speedup vs baseline: 1.2664x; 1.2087x over previous
#include <cuda_runtime.h>
#include <math.h>
#include <cstdint>

#define NSIG   8192
#define DB     512
#define NBAS   2048
#define SCIT   20
#define PMIT   100

__device__ float g_Wf[(size_t)DB * NBAS];    // [512,2048] row-major
__device__ float g_Wt[(size_t)NBAS * DB];    // transpose  [2048,512]
__device__ float g_Wg0t[(size_t)NBAS * DB];  // eta * Wt
__device__ float g_x[2][NBAS];
__device__ float g_t1[DB];
__device__ float g_pmacc[PMIT + 2];
__device__ float g_scal[4];                  // c, 1/c, K/c, K
__device__ float g_nacc[SCIT];
__device__ float g_ysum;
__device__ float g_Z[(size_t)NSIG * NBAS];
__device__ float g_Gamma[(size_t)NSIG * NBAS];
__device__ float g_Gamma2[(size_t)NSIG * NBAS];
__device__ float g_res[(size_t)NSIG * DB];

__device__ __forceinline__ float tf32r(float x) {
    unsigned u; asm("cvt.rna.tf32.f32 %0, %1;" : "=r"(u) : "f"(x));
    return __uint_as_float(u);
}
__device__ __forceinline__ float softf(float x, float lam) {
    float t = fabsf(x) - lam;
    return t > 0.f ? copysignf(t, x) : 0.f;
}
__device__ __forceinline__ unsigned rotl32(unsigned v, int r) { return (v << r) | (v >> (32 - r)); }

__device__ __forceinline__ void mma8(float* c, const unsigned* a, const unsigned* b) {
    asm volatile("mma.sync.aligned.m16n8k8.row.col.f32.tf32.tf32.f32 "
        "{%0,%1,%2,%3},{%4,%5,%6,%7},{%8,%9},{%0,%1,%2,%3};"
        : "+f"(c[0]), "+f"(c[1]), "+f"(c[2]), "+f"(c[3])
        : "r"(a[0]), "r"(a[1]), "r"(a[2]), "r"(a[3]), "r"(b[0]), "r"(b[1]));
}

// jax threefry2x32 with key (0,1)
__device__ __forceinline__ void threefry01(unsigned& x0, unsigned& x1) {
    const unsigned ks0 = 0u, ks1 = 1u, ks2 = 0x1BD11BDBu;
    x0 += ks0; x1 += ks1;
#define TFR(r) { x0 += x1; x1 = rotl32(x1, (r)); x1 ^= x0; }
    TFR(13) TFR(15) TFR(26) TFR(6)   x0 += ks1; x1 += ks2 + 1u;
    TFR(17) TFR(29) TFR(16) TFR(24)  x0 += ks2; x1 += ks0 + 2u;
    TFR(13) TFR(15) TFR(26) TFR(6)   x0 += ks0; x1 += ks1 + 3u;
    TFR(17) TFR(29) TFR(16) TFR(24)  x0 += ks1; x1 += ks2 + 4u;
    TFR(13) TFR(15) TFR(26) TFR(6)   x0 += ks2; x1 += ks0 + 5u;
#undef TFR
}

__device__ float bits_to_normal(unsigned b) {
    float f = __uint_as_float((b >> 9) | 0x3F800000u) - 1.0f;
    const float lo = -0.99999994f;
    float u = fmaxf(lo, fmaf(f, 2.0f, lo));
    float w = -log1pf(-u * u), p;
    if (w < 5.0f) {
        w -= 2.5f;
        p = 2.81022636e-08f;
        p = fmaf(p, w, 3.43273939e-07f);  p = fmaf(p, w, -3.5233877e-06f);
        p = fmaf(p, w, -4.39150654e-06f); p = fmaf(p, w, 0.00021858087f);
        p = fmaf(p, w, -0.00125372503f);  p = fmaf(p, w, -0.00417768164f);
        p = fmaf(p, w, 0.246640727f);     p = fmaf(p, w, 1.50140941f);
    } else {
        w = sqrtf(w) - 3.0f;
        p = -0.000200214257f;
        p = fmaf(p, w, 0.000100950558f);  p = fmaf(p, w, 0.00134934322f);
        p = fmaf(p, w, -0.00367342844f);  p = fmaf(p, w, 0.00573950773f);
        p = fmaf(p, w, -0.0076224613f);   p = fmaf(p, w, 0.00943887047f);
        p = fmaf(p, w, 1.00167406f);      p = fmaf(p, w, 2.83297682f);
    }
    return 1.41421356237f * (p * u);
}

__global__ void k_init() {
    int t = threadIdx.x;
    if (t < PMIT + 2) g_pmacc[t] = 0.f;
    if (t < SCIT)     g_nacc[t]  = 0.f;
    if (t == 0)       g_ysum     = 0.f;
}

__global__ void k_ysum(const float* __restrict__ Y) {
    __shared__ float red[256];
    float s = 0.f;
    for (size_t i = (size_t)blockIdx.x * blockDim.x + threadIdx.x;
         i < (size_t)NSIG * DB; i += (size_t)gridDim.x * blockDim.x) {
        float v = Y[i]; s += v * v;
    }
    red[threadIdx.x] = s; __syncthreads();
    for (int o = 128; o > 0; o >>= 1) {
        if (threadIdx.x < o) red[threadIdx.x] += red[threadIdx.x + o];
        __syncthreads();
    }
    if (threadIdx.x == 0) atomicAdd(&g_ysum, red[0]);
}

__global__ void k_normw(const float* __restrict__ W) {
    int j = blockIdx.x * blockDim.x + threadIdx.x;
    if (j >= NBAS) return;
    float s = 0.f;
    for (int i = 0; i < DB; i++) { float v = W[(size_t)i * NBAS + j]; s += v * v; }
    float n = sqrtf(s);
    for (int i = 0; i < DB; i++) {
        float v = W[(size_t)i * NBAS + j] / n;
        g_Wf[(size_t)i * NBAS + j] = v;
        g_Wt[(size_t)j * DB + i]   = v;
    }
}

__global__ void k_wg0() {
    size_t i = (size_t)blockIdx.x * blockDim.x + threadIdx.x;
    if (i < (size_t)NBAS * DB) g_Wg0t[i] = __fmul_rn(g_scal[1], g_Wt[i]);
}

__global__ void k_x0() {
    int i = blockIdx.x * blockDim.x + threadIdx.x;
    if (i >= NBAS) return;
    unsigned x0 = 0u, x1 = (unsigned)i;
    threefry01(x0, x1);
    g_x[0][i] = bits_to_normal(x0 ^ x1);
}

__global__ void k_pma(int k) {
    __shared__ float xs[NBAS];
    float nm = (k == 1) ? 1.0f : sqrtf(g_pmacc[k - 1]);
    const float* x = g_x[(k - 1) & 1];
    for (int m = threadIdx.x; m < NBAS; m += blockDim.x) xs[m] = x[m] / nm;
    __syncthreads();
    int warp = threadIdx.x >> 5, lane = threadIdx.x & 31;
    int d = blockIdx.x * 8 + warp;
    const float* row = &g_Wf[(size_t)d * NBAS];
    float s = 0.f;
    for (int m = lane; m < NBAS; m += 32) s += xs[m] * row[m];
#pragma unroll
    for (int o = 16; o; o >>= 1) s += __shfl_down_sync(0xffffffffu, s, o);
    if (lane == 0) g_t1[d] = s;
}

__global__ void k_pmb(int k) {
    __shared__ float ts[DB];
    __shared__ float red[256];
    for (int d = threadIdx.x; d < DB; d += blockDim.x) ts[d] = g_t1[d];
    __syncthreads();
    int t = blockIdx.x * blockDim.x + threadIdx.x;
    int m = t >> 2, q = t & 3;
    const float* col = &g_Wf[(size_t)(q * 128) * NBAS + m];
    float v = 0.f;
#pragma unroll 8
    for (int d = 0; d < 128; d++) v += ts[q * 128 + d] * col[(size_t)d * NBAS];
    v += __shfl_xor_sync(0xffffffffu, v, 1);
    v += __shfl_xor_sync(0xffffffffu, v, 2);
    float ssv = 0.f;
    if (q == 0) { g_x[k & 1][m] = v; ssv = v * v; }
    red[threadIdx.x] = ssv; __syncthreads();
    for (int o = 128; o > 0; o >>= 1) {
        if (threadIdx.x < o) red[threadIdx.x] += red[threadIdx.x + o];
        __syncthreads();
    }
    if (threadIdx.x == 0) atomicAdd(&g_pmacc[k], red[0]);
}

__global__ void k_scal(const float* __restrict__ Kp) {
    float c = sqrtf(g_pmacc[PMIT]);
    float K = *Kp;
    g_scal[0] = c; g_scal[1] = 1.0f / c; g_scal[2] = K / c; g_scal[3] = K;
}

__global__ void k_norms(float* __restrict__ out) {
    int i = threadIdx.x;
    if (i < SCIT) out[i] = sqrtf(g_nacc[i]) / sqrtf(g_ysum);
}

// ---------- mma.sync tf32 (3xTF32) GEMM: C[m,n] = dot(A[m0+m,:], B[n0+n,:]) ----------
// A row-major [M,K]; B row-major [N,K] (i.e. we compute A @ B^T). Kd % 16 == 0.
enum { M_PLAIN = 0, M_RES = 1, M_G0 = 2, M_UPD = 3 };
#define LSTR 20   // padded SMEM row stride (floats) — conflict-free for frag pattern

__device__ __forceinline__ void split4(float* Hd, float* Ld, int idx, float4 v) {
    float hx = tf32r(v.x), hy = tf32r(v.y), hz = tf32r(v.z), hw = tf32r(v.w);
    Hd[idx] = hx; Hd[idx+1] = hy; Hd[idx+2] = hz; Hd[idx+3] = hw;
    Ld[idx]   = tf32r(v.x - hx); Ld[idx+1] = tf32r(v.y - hy);
    Ld[idx+2] = tf32r(v.z - hz); Ld[idx+3] = tf32r(v.w - hw);
}

template <int MODE>
__global__ __launch_bounds__(256)
void tgemm(const float* __restrict__ A, const float* __restrict__ B,
           float* __restrict__ C, int Kd, int Nn,
           const float* __restrict__ Yp, float* __restrict__ Zp,
           const float* __restrict__ Gold, float* __restrict__ nacc, float mcoef)
{
    __shared__ __align__(16) float Ah[128 * LSTR], Al[128 * LSTR];
    __shared__ __align__(16) float Bh[128 * LSTR], Bl[128 * LSTR];

    const int tid = threadIdx.x, lane = tid & 31, wid = tid >> 5;
    const int m0 = blockIdx.y * 128, n0 = blockIdx.x * 128;
    const int m0w = (wid >> 2) * 64, n0w = (wid & 3) * 32;
    const int t4 = lane >> 2, tm4 = lane & 3;

    const int lrow = tid >> 2, lcol = (tid & 3) << 2;   // staging: float4 per thread x2
    const float* Ag  = A + (size_t)(m0 + lrow) * Kd + lcol;
    const float* Ag2 = Ag + (size_t)64 * Kd;
    const float* Bg  = B + (size_t)(n0 + lrow) * Kd + lcol;
    const float* Bg2 = Bg + (size_t)64 * Kd;

    float acc[4][4][4] = {};

    float4 va0 = *(const float4*)Ag,  va1 = *(const float4*)Ag2;
    float4 vb0 = *(const float4*)Bg,  vb1 = *(const float4*)Bg2;

    const int KT = Kd >> 4;
    for (int kt = 0; kt < KT; kt++) {
        __syncthreads();
        split4(Ah, Al, lrow * LSTR + lcol, va0);
        split4(Ah, Al, (lrow + 64) * LSTR + lcol, va1);
        split4(Bh, Bl, lrow * LSTR + lcol, vb0);
        split4(Bh, Bl, (lrow + 64) * LSTR + lcol, vb1);
        __syncthreads();
        if (kt + 1 < KT) {
            int ko = (kt + 1) << 4;
            va0 = *(const float4*)(Ag + ko);  va1 = *(const float4*)(Ag2 + ko);
            vb0 = *(const float4*)(Bg + ko);  vb1 = *(const float4*)(Bg2 + ko);
        }
#pragma unroll
        for (int ks = 0; ks < 16; ks += 8) {
            unsigned af[4][4], alf[4][4], bf[4][2], blf[4][2];
#pragma unroll
            for (int mt = 0; mt < 4; mt++) {
                int rb = m0w + mt * 16;
                af[mt][0]  = __float_as_uint(Ah[(rb + t4)     * LSTR + ks + tm4]);
                af[mt][1]  = __float_as_uint(Ah[(rb + t4 + 8) * LSTR + ks + tm4]);
                af[mt][2]  = __float_as_uint(Ah[(rb + t4)     * LSTR + ks + tm4 + 4]);
                af[mt][3]  = __float_as_uint(Ah[(rb + t4 + 8) * LSTR + ks + tm4 + 4]);
                alf[mt][0] = __float_as_uint(Al[(rb + t4)     * LSTR + ks + tm4]);
                alf[mt][1] = __float_as_uint(Al[(rb + t4 + 8) * LSTR + ks + tm4]);
                alf[mt][2] = __float_as_uint(Al[(rb + t4)     * LSTR + ks + tm4 + 4]);
                alf[mt][3] = __float_as_uint(Al[(rb + t4 + 8) * LSTR + ks + tm4 + 4]);
            }
#pragma unroll
            for (int nt = 0; nt < 4; nt++) {
                int cb = n0w + nt * 8 + t4;
                bf[nt][0]  = __float_as_uint(Bh[cb * LSTR + ks + tm4]);
                bf[nt][1]  = __float_as_uint(Bh[cb * LSTR + ks + tm4 + 4]);
                blf[nt][0] = __float_as_uint(Bl[cb * LSTR + ks + tm4]);
                blf[nt][1] = __float_as_uint(Bl[cb * LSTR + ks + tm4 + 4]);
            }
#pragma unroll
            for (int mt = 0; mt < 4; mt++)
#pragma unroll
                for (int nt = 0; nt < 4; nt++) {
                    mma8(acc[mt][nt], af[mt],  bf[nt]);
                    mma8(acc[mt][nt], af[mt],  blf[nt]);
                    mma8(acc[mt][nt], alf[mt], bf[nt]);
                }
        }
    }

    // ---- epilogue ----
    float etav = 0.f, lamv = 0.f, ss = 0.f;
    if (MODE == M_G0)  { lamv = g_scal[3]; }
    if (MODE == M_UPD) { etav = g_scal[1]; lamv = g_scal[2]; }

#pragma unroll
    for (int mt = 0; mt < 4; mt++)
#pragma unroll
        for (int nt = 0; nt < 4; nt++)
#pragma unroll
            for (int hrow = 0; hrow < 2; hrow++) {
                int r = m0 + m0w + mt * 16 + t4 + hrow * 8;
                int cc = n0 + n0w + nt * 8 + 2 * tm4;
                size_t idx = (size_t)r * (size_t)Nn + cc;
                float r0 = acc[mt][nt][hrow * 2], r1 = acc[mt][nt][hrow * 2 + 1];
                if (MODE == M_PLAIN) {
                    *(float2*)&C[idx] = make_float2(r0, r1);
                } else if (MODE == M_RES) {
                    float2 y = *(const float2*)&Yp[idx];
                    float d0 = __fsub_rn(r0, y.x), d1 = __fsub_rn(r1, y.y);
                    *(float2*)&C[idx] = make_float2(d0, d1);
                    ss += d0 * d0 + d1 * d1;
                } else if (MODE == M_G0) {
                    float g0 = softf(r0, lamv), g1 = softf(r1, lamv);
                    *(float2*)&C[idx]  = make_float2(g0, g1);
                    *(float2*)&Zp[idx] = make_float2(g0, g1);
                } else {
                    float2 z  = *(const float2*)&Zp[idx];
                    float2 go = *(const float2*)&Gold[idx];
                    float g0 = softf(__fsub_rn(z.x, __fmul_rn(etav, r0)), lamv);
                    float g1 = softf(__fsub_rn(z.y, __fmul_rn(etav, r1)), lamv);
                    float z0 = __fadd_rn(g0, __fmul_rn(mcoef, __fsub_rn(g0, go.x)));
                    float z1 = __fadd_rn(g1, __fmul_rn(mcoef, __fsub_rn(g1, go.y)));
                    *(float2*)&C[idx]  = make_float2(g0, g1);
                    *(float2*)&Zp[idx] = make_float2(z0, z1);
                }
            }

    if (MODE == M_RES) {
        __syncthreads();
        Ah[tid] = ss; __syncthreads();
        for (int o = 128; o > 0; o >>= 1) {
            if (tid < o) Ah[tid] += Ah[tid + o];
            __syncthreads();
        }
        if (tid == 0) atomicAdd(nacc, Ah[0]);
    }
}

// ---------------- launch ----------------
static float* symaddr(const void* s) {
    void* p = nullptr;
    cudaGetSymbolAddress(&p, s);
    return (float*)p;
}

extern "C" void kernel_launch(void* const* d_in, const int* in_sizes, int n_in,
                              void* d_out, int out_size) {
    const float *Y = nullptr, *W = nullptr, *Kp = nullptr;
    for (int i = 0; i < n_in; i++) {
        if (in_sizes[i] == NSIG * DB)      Y  = (const float*)d_in[i];
        else if (in_sizes[i] == DB * NBAS) W  = (const float*)d_in[i];
        else                               Kp = (const float*)d_in[i];
    }
    float* out  = (float*)d_out;
    float* outX = out;
    float* outG = out + (size_t)NSIG * DB;
    float* outN = outG + (size_t)NSIG * NBAS;

    float* pWf   = symaddr(g_Wf);
    float* pWt   = symaddr(g_Wt);
    float* pWg0t = symaddr(g_Wg0t);
    float* pZ    = symaddr(g_Z);
    float* pRes  = symaddr(g_res);
    float* pNacc = symaddr(g_nacc);
    float* Gbuf[2] = { symaddr(g_Gamma), symaddr(g_Gamma2) };

    k_init<<<1, 256>>>();
    k_normw<<<16, 128>>>(W);
    k_ysum<<<256, 256>>>(Y);
    k_x0<<<8, 256>>>();
    for (int k = 1; k <= PMIT; k++) {
        k_pma<<<64, 256>>>(k);
        k_pmb<<<32, 256>>>(k);
    }
    k_scal<<<1, 1>>>(Kp);
    k_wg0<<<(NBAS * DB + 255) / 256, 256>>>();

    // Gamma0 = soft(Y @ (eta*W), K) -> Gbuf[0], Z
    tgemm<M_G0><<<dim3(16, 64), 256>>>(Y, pWg0t, Gbuf[0], DB, NBAS,
                                       nullptr, pZ, nullptr, nullptr, 0.f);
    float t = 1.0f;
    for (int it = 0; it < SCIT; it++) {
        // residual = Z@W^T - Y ; accumulate ||residual||^2
        tgemm<M_RES><<<dim3(4, 64), 256>>>(pZ, pWf, pRes, NBAS, DB,
                                           Y, nullptr, nullptr, pNacc + it, 0.f);
        float t_new = (1.0f + sqrtf(1.0f + 4.0f * t * t)) * 0.5f;
        float mcoef = (t - 1.0f) / t_new;
        t = t_new;
        float* gold = Gbuf[it & 1];
        float* gout = (it == SCIT - 1) ? outG : Gbuf[(it + 1) & 1];
        // Gamma_new = soft(Z - eta*(res@W), K/c); Z = Gn + mcoef*(Gn - Gold)
        tgemm<M_UPD><<<dim3(16, 64), 256>>>(pRes, pWt, gout, DB, NBAS,
                                            nullptr, pZ, gold, nullptr, mcoef);
    }
    // X = Gamma @ W^T
    tgemm<M_PLAIN><<<dim3(4, 64), 256>>>(outG, pWf, outX, NBAS, DB,
                                         nullptr, nullptr, nullptr, nullptr, 0.f);
    k_norms<<<1, 32>>>(outN);
    (void)out_size;
}